// round 12
// baseline (speedup 1.0000x reference)
#include <cuda_runtime.h>
#include <math.h>

// Problem constants (fixed by the dataset)
#define Bq   2
#define Nc   6
#define Cc   256
#define Mq   900
#define EPSF 1e-5f

#define H0 116
#define W0 200
#define H1 58
#define W1 100
#define H2 29
#define W2 50
#define H3 15
#define W3 25

#define P2 (H2 * W2)     // 1450
#define P3 (H3 * W3)     // 375

#define NT2  (Bq * Nc * 8 * 46)      // 4416 f2 transpose tiles
#define NT3  (Bq * Nc * 8 * 12)      // 1152 f3 transpose tiles
#define NTT  (NT2 + NT3)             // 5568 real transpose tiles
#define NBM  (Bq * Mq)               // 1800 sampler blocks

// Bid interleave: groups of 8 = 7 transpose bids + 1 sampler bid.
#define NGRP   796                    // ceil(5568 / 7)
#define GRID1  (NGRP * 8)             // 6368 mixed-region bids
#define TCOUNT (NGRP * 7)             // 5572 arriving transpose bids (4 no-ops)
#define NS_MIX NGRP                   // 796 samplers inside mixed region (< 888)
#define GRID_TOT (GRID1 + (NBM - NS_MIX))   // 7372

// ---------------- device scratch ----------------
__device__ float g_f2t[Bq * Nc * P2 * Cc];   // pixel-major f2: [bn][px][c]
__device__ float g_f3t[Bq * Nc * P3 * Cc];   // pixel-major f3
__device__ unsigned int g_done;              // transpose completion counter

// ---------------- L0/L1 vectorized gather (proven path) ----------------
__device__ __forceinline__ float pick4(float4 q, int i)
{
    float r = q.w;
    r = (i == 2) ? q.z : r;
    r = (i == 1) ? q.y : r;
    r = (i == 0) ? q.x : r;
    return r;
}

template <int H, int W>
__device__ __forceinline__ void mk_meta4(int bnC, float x0f, float y0f,
                                         int xi, int yi,
                                         int& off, int& i0o, int& spo, int& flags)
{
    bool bx0 = (x0f >= 0.0f)  & (x0f <= (float)(W - 1));
    bool bx1 = (x0f >= -1.0f) & (x0f <= (float)(W - 2));
    bool by0 = (y0f >= 0.0f)  & (y0f <= (float)(H - 1));
    bool by1 = (y0f >= -1.0f) & (y0f <= (float)(H - 2));

    int a = xi & ~3;
    a = (a < 0) ? 0 : a;
    a = (a > W - 4) ? (W - 4) : a;
    int  i0   = xi - a;
    bool sp   = (i0 >= 3);
    bool bxv  = bx1 & !sp;
    bool anyx = bx0 | bxv;
    bool spu  = bx1 & sp;
    int f = 0;
    f |= (by0 & anyx) ? 1  : 0;
    f |= (by1 & anyx) ? 2  : 0;
    f |= bx0          ? 4  : 0;
    f |= bxv          ? 8  : 0;
    f |= (spu & by0)  ? 16 : 0;
    f |= (spu & by1)  ? 32 : 0;
    flags = f;
    off = bnC * (H * W) + yi * W + a;
    i0o = i0;
    spo = bnC * (H * W) + yi * W + xi + 1;
}

template <int H, int W>
__device__ __forceinline__ float use_meta4(const float* __restrict__ f, int c,
                                           int off, int i0, int spo, int flags,
                                           float w00, float w10, float w01, float w11)
{
    float v = 0.0f;
    const float* p = f + c * (H * W) + off;
    if (flags & 1) {
        float4 q = __ldg((const float4*)p);
        if (flags & 4) v += w00 * pick4(q, i0);
        if (flags & 8) v += w10 * pick4(q, i0 + 1);
    }
    if (flags & 2) {
        float4 q = __ldg((const float4*)(p + W));
        if (flags & 4) v += w01 * pick4(q, i0);
        if (flags & 8) v += w11 * pick4(q, i0 + 1);
    }
    if (flags & 16) v += w10 * __ldg(f + c * (H * W) + spo);
    if (flags & 32) v += w11 * __ldg(f + c * (H * W) + spo + W);
    return v;
}

template <int H, int W>
__device__ __forceinline__ int corner_flags(float x0f, float y0f)
{
    bool bx0 = (x0f >= 0.0f)  & (x0f <= (float)(W - 1));
    bool bx1 = (x0f >= -1.0f) & (x0f <= (float)(W - 2));
    bool by0 = (y0f >= 0.0f)  & (y0f <= (float)(H - 1));
    bool by1 = (y0f >= -1.0f) & (y0f <= (float)(H - 2));
    return ((by0 & bx0) ? 1 : 0) | ((by0 & bx1) ? 2 : 0)
         | ((by1 & bx0) ? 4 : 0) | ((by1 & bx1) ? 8 : 0);
}

// ---------------- tiled 32x32 transpose: [C][P] -> [P][C] ----------------
template <int P>
__device__ __forceinline__ void transpose_plane(const float* __restrict__ src,
                                                float* __restrict__ dst,
                                                int ctile, int ptile,
                                                int tx, int ty)
{
    __shared__ float tile[32][33];
    int cb = ctile * 32, pb = ptile * 32;
    #pragma unroll
    for (int j = 0; j < 4; j++) {
        int cc = cb + ty + j * 8;
        int pp = pb + tx;
        tile[ty + j * 8][tx] = (pp < P) ? __ldg(src + cc * P + pp) : 0.0f;
    }
    __syncthreads();
    #pragma unroll
    for (int j = 0; j < 4; j++) {
        int pp = pb + ty + j * 8;
        if (pp < P) dst[pp * Cc + cb + tx] = tile[tx][ty + j * 8];
    }
}

__global__ void reset_kernel() { g_done = 0; }

// =========================================================================
//  Fused kernel with interleaved bids:
//    mixed region (bids [0, GRID1)):  bid%8 < 7 -> transpose, ==7 -> sampler
//    tail region:                      samplers only
// =========================================================================
__global__ void __launch_bounds__(Cc, 6)
fused_kernel(const float* __restrict__ f0,
             const float* __restrict__ f1,
             const float* __restrict__ f2,
             const float* __restrict__ f3,
             const float* __restrict__ refp,
             const float* __restrict__ l2i,
             float* __restrict__ out)
{
    int bid = blockIdx.x;
    int bm;

    if (bid < GRID1) {
        int g = bid >> 3, r = bid & 7;
        if (r < 7) {                       // ---------- transpose bid ----------
            int t = g * 7 + r;
            if (t < NTT) {
                int tx = threadIdx.x & 31, ty = threadIdx.x >> 5;
                if (t < NT2) {
                    int bn = t / (8 * 46);
                    int rr = t % (8 * 46);
                    transpose_plane<P2>(f2 + bn * Cc * P2, g_f2t + bn * P2 * Cc,
                                        rr / 46, rr % 46, tx, ty);
                } else {
                    int u  = t - NT2;
                    int bn = u / (8 * 12);
                    int rr = u % (8 * 12);
                    transpose_plane<P3>(f3 + bn * Cc * P3, g_f3t + bn * P3 * Cc,
                                        rr / 12, rr % 12, tx, ty);
                }
                __syncthreads();
            }
            __threadfence();               // release scratch writes
            if (threadIdx.x == 0) atomicAdd(&g_done, 1u);
            return;
        }
        bm = g;                            // mixed-region sampler
    } else {
        bm = NS_MIX + (bid - GRID1);       // tail sampler
    }

    // ---------- sampler block ----------
    __shared__ int   s_valid[Nc];
    __shared__ float s_w[Nc][4];
    __shared__ int   s_off[Nc][2], s_i0[Nc][2], s_spo[Nc][2], s_flags[Nc][2];
    __shared__ int   s_off2[Nc], s_off3[Nc], s_fl23[Nc];

    int b = bm / Mq;
    int c = threadIdx.x;

    if (c < Nc) {
        int n = c;
        const float* rp = refp + bm * 3;
        float rx = rp[0] * 122.4f - 61.2f;
        float ry = rp[1] * 122.4f - 61.2f;
        float rz = rp[2] * 20.0f  - 10.0f;

        const float* Mt = l2i + (b * Nc + n) * 16;
        float c0 = Mt[0] * rx + Mt[1] * ry + Mt[2]  * rz + Mt[3];
        float c1 = Mt[4] * rx + Mt[5] * ry + Mt[6]  * rz + Mt[7];
        float c2 = Mt[8] * rx + Mt[9] * ry + Mt[10] * rz + Mt[11];

        int valid = (c2 > EPSF) ? 1 : 0;
        s_valid[n] = valid;

        if (valid) {
            float rcp = __fdividef(1.0f, c2 + EPSF);
            // grid-sample normalization cancels: pixel = p - 0.5 at EVERY level
            float x = c0 * rcp - 0.5f;
            float y = c1 * rcp - 0.5f;
            float x0f = floorf(x);
            float y0f = floorf(y);
            float wx1 = x - x0f, wx0 = 1.0f - wx1;
            float wy1 = y - y0f, wy0 = 1.0f - wy1;
            s_w[n][0] = wx0 * wy0; s_w[n][1] = wx1 * wy0;
            s_w[n][2] = wx0 * wy1; s_w[n][3] = wx1 * wy1;

            int xi = (int)fmaxf(fminf(x0f, 1.0e8f), -1.0e8f);
            int yi = (int)fmaxf(fminf(y0f, 1.0e8f), -1.0e8f);
            int bnC = (b * Nc + n) * Cc;
            mk_meta4<H0, W0>(bnC, x0f, y0f, xi, yi,
                             s_off[n][0], s_i0[n][0], s_spo[n][0], s_flags[n][0]);
            mk_meta4<H1, W1>(bnC, x0f, y0f, xi, yi,
                             s_off[n][1], s_i0[n][1], s_spo[n][1], s_flags[n][1]);

            // f2t/f3t meta (pixel-major). Clamp keeps offsets small; identity
            // whenever any corner flag is set.
            s_fl23[n] = corner_flags<H2, W2>(x0f, y0f)
                      | (corner_flags<H3, W3>(x0f, y0f) << 4);
            int xc = min(max(xi, -4), 64);
            int yc = min(max(yi, -4), 40);
            int bn = b * Nc + n;
            s_off2[n] = (bn * P2 + yc * W2 + xc) * Cc;
            s_off3[n] = (bn * P3 + yc * W3 + xc) * Cc;
        } else {
            s_flags[n][0] = 0; s_flags[n][1] = 0; s_fl23[n] = 0;
        }
    }
    __syncthreads();

    int cnt = s_valid[0] + s_valid[1] + s_valid[2]
            + s_valid[3] + s_valid[4] + s_valid[5];
    float inv = __fdividef(0.25f, (float)cnt + EPSF);

    // ---- L0 + L1 gathers (long phase; transposes drain concurrently) ----
    float acc = 0.0f;
    #pragma unroll
    for (int n = 0; n < Nc; n++) {
        if (!s_valid[n]) continue;   // warp-uniform
        float w00 = s_w[n][0], w10 = s_w[n][1];
        float w01 = s_w[n][2], w11 = s_w[n][3];
        acc += use_meta4<H0, W0>(f0, c, s_off[n][0], s_i0[n][0], s_spo[n][0],
                                 s_flags[n][0], w00, w10, w01, w11);
        acc += use_meta4<H1, W1>(f1, c, s_off[n][1], s_i0[n][1], s_spo[n][1],
                                 s_flags[n][1], w00, w10, w01, w11);
    }

    // ---- wait for all transpose bids (normally already complete) ----
    if (threadIdx.x == 0) {
        while (atomicAdd(&g_done, 0u) < (unsigned)TCOUNT) { __nanosleep(64); }
    }
    __syncthreads();
    __threadfence();                 // acquire: order scratch reads after wait

    // ---- f2t / f3t sampling (fully coalesced channel loads) ----
    #pragma unroll
    for (int n = 0; n < Nc; n++) {
        int fl = s_fl23[n];
        if (!fl) continue;           // warp-uniform
        float w00 = s_w[n][0], w10 = s_w[n][1];
        float w01 = s_w[n][2], w11 = s_w[n][3];

        const float* p2 = g_f2t + s_off2[n] + c;
        if (fl & 1) acc += w00 * __ldg(p2);
        if (fl & 2) acc += w10 * __ldg(p2 + Cc);
        if (fl & 4) acc += w01 * __ldg(p2 + W2 * Cc);
        if (fl & 8) acc += w11 * __ldg(p2 + (W2 + 1) * Cc);

        const float* p3 = g_f3t + s_off3[n] + c;
        if (fl & 16)  acc += w00 * __ldg(p3);
        if (fl & 32)  acc += w10 * __ldg(p3 + Cc);
        if (fl & 64)  acc += w01 * __ldg(p3 + W3 * Cc);
        if (fl & 128) acc += w11 * __ldg(p3 + (W3 + 1) * Cc);
    }

    out[bm * Cc + c] = acc * inv;
}

// ---------------- host ----------------
extern "C" void kernel_launch(void* const* d_in, const int* in_sizes, int n_in,
                              void* d_out, int out_size)
{
    const float* f0   = (const float*)d_in[0];
    const float* f1   = (const float*)d_in[1];
    const float* f2   = (const float*)d_in[2];
    const float* f3   = (const float*)d_in[3];
    const float* refp = (const float*)d_in[4];
    const float* l2i  = (const float*)d_in[5];
    float* out = (float*)d_out;

    reset_kernel<<<1, 1>>>();
    fused_kernel<<<GRID_TOT, Cc>>>(f0, f1, f2, f3, refp, l2i, out);
}

// round 13
// speedup vs baseline: 1.9453x; 1.9453x over previous
#include <cuda_runtime.h>
#include <math.h>

// Problem constants (fixed by the dataset)
#define Bq   2
#define Nc   6
#define Cc   256
#define Mq   900
#define EPSF 1e-5f

#define H0 116
#define W0 200
#define H1 58
#define W1 100
#define H2 29
#define W2 50
#define H3 15
#define W3 25

#define P2 (H2 * W2)     // 1450
#define P3 (H3 * W3)     // 375

#define NBM  (Bq * Mq)               // 1800 sampler blocks
#define NT2  (Bq * Nc * 8 * 46)      // 4416 f2 transpose tiles
#define NT3  (Bq * Nc * 8 * 12)      // 1152 f3 transpose tiles

// ---------------- device scratch ----------------
__device__ float  g_f2t[Bq * Nc * P2 * Cc];   // pixel-major f2: [bn][px][c]
__device__ float  g_f3t[Bq * Nc * P3 * Cc];   // pixel-major f3
__device__ float4 g_mw[NBM * Nc];             // prescaled bilinear weights
__device__ int4   g_mi[NBM * Nc];             // {off2, off3, flags, 0}

// ---------------- L0/L1 vectorized gather (proven path) ----------------
__device__ __forceinline__ float pick4(float4 q, int i)
{
    float r = q.w;
    r = (i == 2) ? q.z : r;
    r = (i == 1) ? q.y : r;
    r = (i == 0) ? q.x : r;
    return r;
}

template <int H, int W>
__device__ __forceinline__ void mk_meta4(int bnC, float x0f, float y0f,
                                         int xi, int yi,
                                         int& off, int& i0o, int& spo, int& flags)
{
    bool bx0 = (x0f >= 0.0f)  & (x0f <= (float)(W - 1));
    bool bx1 = (x0f >= -1.0f) & (x0f <= (float)(W - 2));
    bool by0 = (y0f >= 0.0f)  & (y0f <= (float)(H - 1));
    bool by1 = (y0f >= -1.0f) & (y0f <= (float)(H - 2));

    int a = xi & ~3;
    a = (a < 0) ? 0 : a;
    a = (a > W - 4) ? (W - 4) : a;
    int  i0   = xi - a;
    bool sp   = (i0 >= 3);
    bool bxv  = bx1 & !sp;
    bool anyx = bx0 | bxv;
    bool spu  = bx1 & sp;
    int f = 0;
    f |= (by0 & anyx) ? 1  : 0;
    f |= (by1 & anyx) ? 2  : 0;
    f |= bx0          ? 4  : 0;
    f |= bxv          ? 8  : 0;
    f |= (spu & by0)  ? 16 : 0;
    f |= (spu & by1)  ? 32 : 0;
    flags = f;
    off = bnC * (H * W) + yi * W + a;
    i0o = i0;
    spo = bnC * (H * W) + yi * W + xi + 1;
}

template <int H, int W>
__device__ __forceinline__ float use_meta4(const float* __restrict__ f, int c,
                                           int off, int i0, int spo, int flags,
                                           float w00, float w10, float w01, float w11)
{
    float v = 0.0f;
    const float* p = f + c * (H * W) + off;
    if (flags & 1) {
        float4 q = __ldg((const float4*)p);
        if (flags & 4) v += w00 * pick4(q, i0);
        if (flags & 8) v += w10 * pick4(q, i0 + 1);
    }
    if (flags & 2) {
        float4 q = __ldg((const float4*)(p + W));
        if (flags & 4) v += w01 * pick4(q, i0);
        if (flags & 8) v += w11 * pick4(q, i0 + 1);
    }
    if (flags & 16) v += w10 * __ldg(f + c * (H * W) + spo);
    if (flags & 32) v += w11 * __ldg(f + c * (H * W) + spo + W);
    return v;
}

template <int H, int W>
__device__ __forceinline__ int corner_flags(float x0f, float y0f)
{
    bool bx0 = (x0f >= 0.0f)  & (x0f <= (float)(W - 1));
    bool bx1 = (x0f >= -1.0f) & (x0f <= (float)(W - 2));
    bool by0 = (y0f >= 0.0f)  & (y0f <= (float)(H - 1));
    bool by1 = (y0f >= -1.0f) & (y0f <= (float)(H - 2));
    return ((by0 & bx0) ? 1 : 0) | ((by0 & bx1) ? 2 : 0)
         | ((by1 & bx0) ? 4 : 0) | ((by1 & bx1) ? 8 : 0);
}

// ---------------- tiled 32x32 transpose: [C][P] -> [P][C] ----------------
template <int P>
__device__ __forceinline__ void transpose_plane(const float* __restrict__ src,
                                                float* __restrict__ dst,
                                                int ctile, int ptile,
                                                int tx, int ty)
{
    __shared__ float tile[32][33];
    int cb = ctile * 32, pb = ptile * 32;
    #pragma unroll
    for (int j = 0; j < 4; j++) {
        int cc = cb + ty + j * 8;
        int pp = pb + tx;
        tile[ty + j * 8][tx] = (pp < P) ? __ldg(src + cc * P + pp) : 0.0f;
    }
    __syncthreads();
    #pragma unroll
    for (int j = 0; j < 4; j++) {
        int pp = pb + ty + j * 8;
        if (pp < P) dst[pp * Cc + cb + tx] = tile[tx][ty + j * 8];
    }
}

// =========================================================================
//  Kernel 1 (identical to round 9): samplers at LOW bids, transposes HIGH
// =========================================================================
__global__ void __launch_bounds__(Cc)
kernel1(const float* __restrict__ f0,
        const float* __restrict__ f1,
        const float* __restrict__ f2,
        const float* __restrict__ f3,
        const float* __restrict__ refp,
        const float* __restrict__ l2i,
        float* __restrict__ out)
{
    int bid = blockIdx.x;

    if (bid >= NBM) {                      // ---------- transpose blocks ----------
        int tx = threadIdx.x & 31, ty = threadIdx.x >> 5;
        int t = bid - NBM;
        if (t < NT2) {
            int bn = t / (8 * 46);
            int r  = t % (8 * 46);
            transpose_plane<P2>(f2 + bn * Cc * P2, g_f2t + bn * P2 * Cc,
                                r / 46, r % 46, tx, ty);
        } else {
            t -= NT2;
            int bn = t / (8 * 12);
            int r  = t % (8 * 12);
            transpose_plane<P3>(f3 + bn * Cc * P3, g_f3t + bn * P3 * Cc,
                                r / 12, r % 12, tx, ty);
        }
        return;
    }

    // ---------- sampler block ----------
    __shared__ int   s_valid[Nc];
    __shared__ float s_w[Nc][4];
    __shared__ int   s_off[Nc][2], s_i0[Nc][2], s_spo[Nc][2], s_flags[Nc][2];

    int bm = bid;
    int b  = bm / Mq;
    int c  = threadIdx.x;

    float rw0 = 0, rw1 = 0, rw2 = 0, rw3 = 0;
    int   roff2 = 0, roff3 = 0, rfl = 0;

    if (c < Nc) {
        int n = c;
        const float* rp = refp + bm * 3;
        float rx = rp[0] * 122.4f - 61.2f;
        float ry = rp[1] * 122.4f - 61.2f;
        float rz = rp[2] * 20.0f  - 10.0f;

        const float* Mt = l2i + (b * Nc + n) * 16;
        float c0 = Mt[0] * rx + Mt[1] * ry + Mt[2]  * rz + Mt[3];
        float c1 = Mt[4] * rx + Mt[5] * ry + Mt[6]  * rz + Mt[7];
        float c2 = Mt[8] * rx + Mt[9] * ry + Mt[10] * rz + Mt[11];

        int valid = (c2 > EPSF) ? 1 : 0;
        s_valid[n] = valid;

        if (valid) {
            float rcp = __fdividef(1.0f, c2 + EPSF);
            // grid-sample normalization cancels: pixel = p - 0.5 at EVERY level
            float x = c0 * rcp - 0.5f;
            float y = c1 * rcp - 0.5f;
            float x0f = floorf(x);
            float y0f = floorf(y);
            float wx1 = x - x0f, wx0 = 1.0f - wx1;
            float wy1 = y - y0f, wy0 = 1.0f - wy1;
            rw0 = wx0 * wy0; rw1 = wx1 * wy0;
            rw2 = wx0 * wy1; rw3 = wx1 * wy1;
            s_w[n][0] = rw0; s_w[n][1] = rw1;
            s_w[n][2] = rw2; s_w[n][3] = rw3;

            int xi = (int)fmaxf(fminf(x0f, 1.0e8f), -1.0e8f);
            int yi = (int)fmaxf(fminf(y0f, 1.0e8f), -1.0e8f);
            int bnC = (b * Nc + n) * Cc;
            mk_meta4<H0, W0>(bnC, x0f, y0f, xi, yi,
                             s_off[n][0], s_i0[n][0], s_spo[n][0], s_flags[n][0]);
            mk_meta4<H1, W1>(bnC, x0f, y0f, xi, yi,
                             s_off[n][1], s_i0[n][1], s_spo[n][1], s_flags[n][1]);

            rfl = corner_flags<H2, W2>(x0f, y0f)
                | (corner_flags<H3, W3>(x0f, y0f) << 4);
            int xc = min(max(xi, -4), 64);
            int yc = min(max(yi, -4), 40);
            int bn = b * Nc + n;
            roff2 = (bn * P2 + yc * W2 + xc) * Cc;
            roff3 = (bn * P3 + yc * W3 + xc) * Cc;
        } else {
            s_flags[n][0] = 0; s_flags[n][1] = 0;
        }
    }
    __syncthreads();

    int cnt = s_valid[0] + s_valid[1] + s_valid[2]
            + s_valid[3] + s_valid[4] + s_valid[5];
    float inv = __fdividef(0.25f, (float)cnt + EPSF);

    if (c < Nc) {
        int idx = bm * Nc + c;
        float4 wv;
        wv.x = rw0 * inv; wv.y = rw1 * inv;
        wv.z = rw2 * inv; wv.w = rw3 * inv;
        g_mw[idx] = wv;
        int4 iv; iv.x = roff2; iv.y = roff3; iv.z = rfl; iv.w = 0;
        g_mi[idx] = iv;
    }

    float acc = 0.0f;
    #pragma unroll
    for (int n = 0; n < Nc; n++) {
        if (!s_valid[n]) continue;   // warp-uniform
        float w00 = s_w[n][0], w10 = s_w[n][1];
        float w01 = s_w[n][2], w11 = s_w[n][3];
        acc += use_meta4<H0, W0>(f0, c, s_off[n][0], s_i0[n][0], s_spo[n][0],
                                 s_flags[n][0], w00, w10, w01, w11);
        acc += use_meta4<H1, W1>(f1, c, s_off[n][1], s_i0[n][1], s_spo[n][1],
                                 s_flags[n][1], w00, w10, w01, w11);
    }

    out[bm * Cc + c] = acc * inv;    // kernel2 adds f2/f3 on top
}

// =========================================================================
//  Kernel 2: f2/f3 from pixel-major copies, LDG.128 over 4 channels.
//  grid = NBM/4 blocks x 256 threads; thread = (query q = tid/64,
//  channel-group cg = tid%64 covering channels 4*cg .. 4*cg+3).
//  4x fewer load instructions than the scalar version (LSU-issue floor /4).
// =========================================================================
__global__ void __launch_bounds__(256)
kernel2(float* __restrict__ out)
{
    int q  = threadIdx.x >> 6;          // 0..3  (query within block)
    int cg = threadIdx.x & 63;          // 0..63 (channel group)
    int c  = cg * 4;
    int bm = blockIdx.x * 4 + q;

    float4 acc = make_float4(0.f, 0.f, 0.f, 0.f);

    #pragma unroll
    for (int n = 0; n < Nc; n++) {
        int4   iv = __ldg(&g_mi[bm * Nc + n]);   // broadcast within warp
        int fl = iv.z;
        if (!fl) continue;                        // warp-uniform skip
        float4 wv = __ldg(&g_mw[bm * Nc + n]);

        const float* p2 = g_f2t + iv.x + c;
        if (fl & 1) {
            float4 v = __ldg((const float4*)p2);
            acc.x += wv.x * v.x; acc.y += wv.x * v.y;
            acc.z += wv.x * v.z; acc.w += wv.x * v.w;
        }
        if (fl & 2) {
            float4 v = __ldg((const float4*)(p2 + Cc));
            acc.x += wv.y * v.x; acc.y += wv.y * v.y;
            acc.z += wv.y * v.z; acc.w += wv.y * v.w;
        }
        if (fl & 4) {
            float4 v = __ldg((const float4*)(p2 + W2 * Cc));
            acc.x += wv.z * v.x; acc.y += wv.z * v.y;
            acc.z += wv.z * v.z; acc.w += wv.z * v.w;
        }
        if (fl & 8) {
            float4 v = __ldg((const float4*)(p2 + (W2 + 1) * Cc));
            acc.x += wv.w * v.x; acc.y += wv.w * v.y;
            acc.z += wv.w * v.z; acc.w += wv.w * v.w;
        }

        const float* p3 = g_f3t + iv.y + c;
        if (fl & 16) {
            float4 v = __ldg((const float4*)p3);
            acc.x += wv.x * v.x; acc.y += wv.x * v.y;
            acc.z += wv.x * v.z; acc.w += wv.x * v.w;
        }
        if (fl & 32) {
            float4 v = __ldg((const float4*)(p3 + Cc));
            acc.x += wv.y * v.x; acc.y += wv.y * v.y;
            acc.z += wv.y * v.z; acc.w += wv.y * v.w;
        }
        if (fl & 64) {
            float4 v = __ldg((const float4*)(p3 + W3 * Cc));
            acc.x += wv.z * v.x; acc.y += wv.z * v.y;
            acc.z += wv.z * v.z; acc.w += wv.z * v.w;
        }
        if (fl & 128) {
            float4 v = __ldg((const float4*)(p3 + (W3 + 1) * Cc));
            acc.x += wv.w * v.x; acc.y += wv.w * v.y;
            acc.z += wv.w * v.z; acc.w += wv.w * v.w;
        }
    }

    float4* po = (float4*)(out + bm * Cc + c);
    float4 o = *po;
    o.x += acc.x; o.y += acc.y; o.z += acc.z; o.w += acc.w;
    *po = o;
}

// ---------------- host ----------------
extern "C" void kernel_launch(void* const* d_in, const int* in_sizes, int n_in,
                              void* d_out, int out_size)
{
    const float* f0   = (const float*)d_in[0];
    const float* f1   = (const float*)d_in[1];
    const float* f2   = (const float*)d_in[2];
    const float* f3   = (const float*)d_in[3];
    const float* refp = (const float*)d_in[4];
    const float* l2i  = (const float*)d_in[5];
    float* out = (float*)d_out;

    kernel1<<<NBM + NT2 + NT3, Cc>>>(f0, f1, f2, f3, refp, l2i, out);
    kernel2<<<NBM / 4, 256>>>(out);
}